// round 5
// baseline (speedup 1.0000x reference)
#include <cuda_runtime.h>
#include <cstdint>

// Problem shape (fixed per reference)
#define N_CASES 6
#define ROWS 16384
#define COLS 4096
#define SLAB_ELEMS (ROWS * COLS)            // 67,108,864 floats (fits int32)
#define SLAB_VEC4  (SLAB_ELEMS / 4)         // 16,777,216 float4
#define SLAB_VEC8  (SLAB_ELEMS / 8)         //  8,388,608 32-byte units

// 96 MiB of the source slab pinned in L2 (evict_last) across graph replays.
// 96 MiB / 126 MB L2 = 76% — leaves headroom for the streaming traffic.
#define PIN_BYTES (96 * 1024 * 1024)
#define PIN_VEC8  (PIN_BYTES / 32)          // 3,145,728 32B units
#define PIN_VEC4  (PIN_BYTES / 16)          // 6,291,456 float4 units

struct v256 { unsigned long long a, b, c, d; };

// 256-bit load with L2 evict_last (sm_103a requires .v4.b64/.v8.b32 width
// for this hint). Pins the line in L2 across graph replays.
__device__ __forceinline__ v256 ldg_pin256(const void* p) {
    v256 v;
    asm volatile("ld.global.nc.L2::evict_last.v4.u64 {%0,%1,%2,%3}, [%4];"
                 : "=l"(v.a), "=l"(v.b), "=l"(v.c), "=l"(v.d) : "l"(p));
    return v;
}

__device__ __forceinline__ void stcs2(float4* dst4, const v256& v) {
    float4 lo, hi;
    lo.x = __ull2float_rz(0);  // placeholder, overwritten below via bitcast
    // Bit-exact reinterpret of the four u64s into two float4s.
    unsigned long long t;
    t = v.a; lo.x = __uint_as_float((unsigned)(t)); lo.y = __uint_as_float((unsigned)(t >> 32));
    t = v.b; lo.z = __uint_as_float((unsigned)(t)); lo.w = __uint_as_float((unsigned)(t >> 32));
    t = v.c; hi.x = __uint_as_float((unsigned)(t)); hi.y = __uint_as_float((unsigned)(t >> 32));
    t = v.d; hi.z = __uint_as_float((unsigned)(t)); hi.w = __uint_as_float((unsigned)(t >> 32));
    __stcs(dst4,     lo);
    __stcs(dst4 + 1, hi);
}

__global__ __launch_bounds__(256, 6)
void select_copy_kernel(const float* __restrict__ x,
                        const float* __restrict__ fingerprints,
                        const float* __restrict__ cached_outputs,
                        float* __restrict__ out) {
    __shared__ int s_idx;

    // Every block independently computes the selected index (28 loads).
    if (threadIdx.x == 0) {
        float p0 = x[0], p1 = x[1], p2 = x[2], p3 = x[3];
        int idx = 0;
        // Scan high->low so the LOWEST matching index survives (first match
        // wins). No match -> 0, matching reference argmax semantics.
        #pragma unroll
        for (int c = N_CASES - 1; c >= 0; --c) {
            const float* f = fingerprints + 4 * c;
            if (p0 == f[0] && p1 == f[1] && p2 == f[2] && p3 == f[3]) {
                idx = c;
            }
        }
        s_idx = idx;
    }
    __syncthreads();

    const float* src_base = cached_outputs + (long long)s_idx * SLAB_ELEMS;
    float4* __restrict__ dst = reinterpret_cast<float4*>(out);

    const int stride = gridDim.x * blockDim.x;          // 888*256 = 227,328
    const int tid = blockIdx.x * blockDim.x + threadIdx.x;

    // ── Phase 1: pinned prefix [0, 96 MiB) — 256-bit evict_last loads stick
    //    in L2 and serve subsequent graph replays from L2 instead of DRAM.
    {
        const char* src8 = reinterpret_cast<const char*>(src_base);
        int i = tid;
        const int end2 = PIN_VEC8 - stride;
        for (; i < end2; i += 2 * stride) {
            v256 v0 = ldg_pin256(src8 + (long long)i * 32);
            v256 v1 = ldg_pin256(src8 + (long long)(i + stride) * 32);
            stcs2(dst + 2 * i,                v0);
            stcs2(dst + 2 * (i + stride),     v1);
        }
        for (; i < PIN_VEC8; i += stride) {
            v256 v = ldg_pin256(src8 + (long long)i * 32);
            stcs2(dst + 2 * i, v);
        }
    }

    // ── Phase 2: streaming tail [96 MiB, 256 MiB) — evict_first both ways
    //    so this traffic never displaces the pinned set.
    {
        const float4* src4 = reinterpret_cast<const float4*>(src_base);
        int i = PIN_VEC4 + tid;
        const int end4 = SLAB_VEC4 - 3 * stride;
        for (; i < end4; i += 4 * stride) {
            float4 v0 = __ldcs(src4 + i);
            float4 v1 = __ldcs(src4 + i + stride);
            float4 v2 = __ldcs(src4 + i + 2 * stride);
            float4 v3 = __ldcs(src4 + i + 3 * stride);
            __stcs(dst + i,              v0);
            __stcs(dst + i + stride,     v1);
            __stcs(dst + i + 2 * stride, v2);
            __stcs(dst + i + 3 * stride, v3);
        }
        for (; i < SLAB_VEC4; i += stride) {
            __stcs(dst + i, __ldcs(src4 + i));
        }
    }
}

extern "C" void kernel_launch(void* const* d_in, const int* in_sizes, int n_in,
                              void* d_out, int out_size) {
    const float* x              = (const float*)d_in[0];
    const float* fingerprints   = (const float*)d_in[1];
    const float* cached_outputs = (const float*)d_in[2];
    float* out = (float*)d_out;

    const int threads = 256;
    const int blocks  = 148 * 6;   // 6 resident CTAs/SM -> exactly one wave
    select_copy_kernel<<<blocks, threads>>>(x, fingerprints, cached_outputs, out);
}

// round 6
// speedup vs baseline: 1.0209x; 1.0209x over previous
#include <cuda_runtime.h>
#include <cstdint>

// Problem shape (fixed per reference)
#define N_CASES 6
#define SLAB_ELEMS 67108864LL                // 16384*4096 floats
#define SLAB_BYTES 268435456LL               // 256 MiB

#define CHUNK 32768                          // 32 KiB per bulk transfer
#define NBUF 4                               // 4 smem buffers = 128 KiB
#define LOOKAHEAD 3                          // loads in flight
#define NCHUNKS 8192                         // SLAB_BYTES / CHUNK
#define GRID 152                             // GB300: 152 SMs, 1 CTA each
#define SMEM_BYTES (NBUF * CHUNK + NBUF * 8) // buffers + mbarriers

__global__ __launch_bounds__(32, 1)
void tma_copy_kernel(const float* __restrict__ x,
                     const float* __restrict__ fingerprints,
                     const float* __restrict__ cached_outputs,
                     float* __restrict__ out) {
    extern __shared__ __align__(128) char smem[];
    if (threadIdx.x != 0) return;   // single orchestrator thread per CTA

    // ── Content-addressed select (28 scalar loads, negligible).
    float p0 = x[0], p1 = x[1], p2 = x[2], p3 = x[3];
    int idx = 0;
    // Scan high->low so the LOWEST matching index survives; no match -> 0.
    #pragma unroll
    for (int c = N_CASES - 1; c >= 0; --c) {
        const float* f = fingerprints + 4 * c;
        if (p0 == f[0] && p1 == f[1] && p2 == f[2] && p3 == f[3]) idx = c;
    }

    const char* __restrict__ src =
        (const char*)cached_outputs + (long long)idx * SLAB_BYTES;
    char* __restrict__ dst = (char*)out;

    uint32_t sbase;
    asm("{ .reg .u64 t; cvta.to.shared.u64 t, %1; cvt.u32.u64 %0, t; }"
        : "=r"(sbase) : "l"(smem));
    const uint32_t mb_base = sbase + NBUF * CHUNK;

    #pragma unroll
    for (int b = 0; b < NBUF; ++b)
        asm volatile("mbarrier.init.shared.b64 [%0], 1;"
                     :: "r"(mb_base + b * 8) : "memory");
    asm volatile("fence.proxy.async.shared::cta;" ::: "memory");

    const long long c0   = (long long)blockIdx.x * CHUNK;
    const long long step = (long long)GRID * CHUNK;
    const int n = (int)((NCHUNKS - (long long)blockIdx.x + GRID - 1) / GRID);

    // ── Prologue: fill the pipeline with LOOKAHEAD bulk loads.
    const int pre = n < LOOKAHEAD ? n : LOOKAHEAD;
    for (int j = 0; j < pre; ++j) {
        uint32_t mb = mb_base + (j & (NBUF - 1)) * 8;
        uint32_t sb = sbase   + (j & (NBUF - 1)) * CHUNK;
        asm volatile("mbarrier.arrive.expect_tx.shared.b64 _, [%0], %1;"
                     :: "r"(mb), "r"(CHUNK) : "memory");
        asm volatile(
            "cp.async.bulk.shared::cta.global.mbarrier::complete_tx::bytes "
            "[%0], [%1], %2, [%3];"
            :: "r"(sb), "l"(src + c0 + (long long)j * step), "r"(CHUNK), "r"(mb)
            : "memory");
    }

    // ── Steady state.
    for (int j = 0; j < n; ++j) {
        const int buf = j & (NBUF - 1);
        const uint32_t mb = mb_base + buf * 8;
        const uint32_t sb = sbase   + buf * CHUNK;
        const uint32_t parity = (uint32_t)(j >> 2) & 1u;

        // Wait for load j to land in smem.
        uint32_t done;
        asm volatile(
            "{\n\t.reg .pred p;\n\t"
            "mbarrier.try_wait.parity.acquire.cta.shared::cta.b64 p, [%1], %2;\n\t"
            "selp.b32 %0, 1, 0, p;\n\t}"
            : "=r"(done) : "r"(mb), "r"(parity) : "memory");
        if (!done) {
            asm volatile(
                "{\n\t.reg .pred P1;\n\t"
                "WAIT_LOOP_%=:\n\t"
                "mbarrier.try_wait.parity.acquire.cta.shared::cta.b64 P1, [%0], %1, 0x989680;\n\t"
                "@P1 bra.uni WAIT_DONE_%=;\n\t"
                "bra.uni WAIT_LOOP_%=;\n\t"
                "WAIT_DONE_%=:\n\t}"
                :: "r"(mb), "r"(parity) : "memory");
        }

        // Bulk store j (async, fire-and-forget into its own bulk group).
        asm volatile(
            "cp.async.bulk.global.shared::cta.bulk_group [%0], [%1], %2;"
            :: "l"(dst + c0 + (long long)j * step), "r"(sb), "r"(CHUNK)
            : "memory");
        asm volatile("cp.async.bulk.commit_group;" ::: "memory");

        // Refill the pipeline: load j+LOOKAHEAD reuses buffer (j-1)&3, whose
        // store was committed last iteration. wait_group.read 1 guarantees all
        // stores except the newest have finished READING smem (writes to
        // global keep flowing asynchronously).
        const int jn = j + LOOKAHEAD;
        if (jn < n) {
            asm volatile("cp.async.bulk.wait_group.read 1;" ::: "memory");
            const uint32_t mb2 = mb_base + (jn & (NBUF - 1)) * 8;
            const uint32_t sb2 = sbase   + (jn & (NBUF - 1)) * CHUNK;
            asm volatile("mbarrier.arrive.expect_tx.shared.b64 _, [%0], %1;"
                         :: "r"(mb2), "r"(CHUNK) : "memory");
            asm volatile(
                "cp.async.bulk.shared::cta.global.mbarrier::complete_tx::bytes "
                "[%0], [%1], %2, [%3];"
                :: "r"(sb2), "l"(src + c0 + (long long)jn * step), "r"(CHUNK),
                   "r"(mb2)
                : "memory");
        }
    }

    // All bulk stores must fully complete (global writes done) before exit.
    asm volatile("cp.async.bulk.wait_group 0;" ::: "memory");
}

extern "C" void kernel_launch(void* const* d_in, const int* in_sizes, int n_in,
                              void* d_out, int out_size) {
    const float* x              = (const float*)d_in[0];
    const float* fingerprints   = (const float*)d_in[1];
    const float* cached_outputs = (const float*)d_in[2];
    float* out = (float*)d_out;

    static bool attr_set = false;
    if (!attr_set) {
        cudaFuncSetAttribute(tma_copy_kernel,
                             cudaFuncAttributeMaxDynamicSharedMemorySize,
                             SMEM_BYTES);
        attr_set = true;
    }
    tma_copy_kernel<<<GRID, 32, SMEM_BYTES>>>(x, fingerprints, cached_outputs,
                                              out);
}

// round 7
// speedup vs baseline: 1.0285x; 1.0075x over previous
#include <cuda_runtime.h>
#include <cstdint>

// Problem shape (fixed per reference)
#define N_CASES 6
#define SLAB_BYTES 268435456LL               // 256 MiB

#define CHUNK 65536                          // 64 KiB per bulk transfer
#define NBUF 3                               // 3 smem buffers = 192 KiB
#define LOOKAHEAD 2                          // loads in flight
#define NCHUNKS 4096                         // SLAB_BYTES / CHUNK
#define GRID 152                             // GB300: 152 SMs, 1 CTA each
#define SMEM_BYTES (NBUF * CHUNK + NBUF * 8) // buffers + mbarriers

__global__ __launch_bounds__(32, 1)
void tma_copy_kernel(const float* __restrict__ x,
                     const float* __restrict__ fingerprints,
                     const float* __restrict__ cached_outputs,
                     float* __restrict__ out) {
    extern __shared__ __align__(128) char smem[];
    if (threadIdx.x != 0) return;   // single orchestrator thread per CTA

    // ── Content-addressed select (28 scalar loads, negligible).
    float p0 = x[0], p1 = x[1], p2 = x[2], p3 = x[3];
    int idx = 0;
    // Scan high->low so the LOWEST matching index survives; no match -> 0.
    #pragma unroll
    for (int c = N_CASES - 1; c >= 0; --c) {
        const float* f = fingerprints + 4 * c;
        if (p0 == f[0] && p1 == f[1] && p2 == f[2] && p3 == f[3]) idx = c;
    }

    const char* __restrict__ src =
        (const char*)cached_outputs + (long long)idx * SLAB_BYTES;
    char* __restrict__ dst = (char*)out;

    uint32_t sbase;
    asm("{ .reg .u64 t; cvta.to.shared.u64 t, %1; cvt.u32.u64 %0, t; }"
        : "=r"(sbase) : "l"(smem));
    const uint32_t mb_base = sbase + NBUF * CHUNK;

    #pragma unroll
    for (int b = 0; b < NBUF; ++b)
        asm volatile("mbarrier.init.shared.b64 [%0], 1;"
                     :: "r"(mb_base + b * 8) : "memory");
    asm volatile("fence.proxy.async.shared::cta;" ::: "memory");

    const long long c0   = (long long)blockIdx.x * CHUNK;
    const long long step = (long long)GRID * CHUNK;
    const int n = (int)((NCHUNKS - (long long)blockIdx.x + GRID - 1) / GRID);

    // ── Prologue: fill the pipeline with LOOKAHEAD bulk loads.
    const int pre = n < LOOKAHEAD ? n : LOOKAHEAD;
    for (int j = 0; j < pre; ++j) {
        const int buf = j % NBUF;
        uint32_t mb = mb_base + buf * 8;
        uint32_t sb = sbase   + buf * CHUNK;
        asm volatile("mbarrier.arrive.expect_tx.shared.b64 _, [%0], %1;"
                     :: "r"(mb), "r"(CHUNK) : "memory");
        asm volatile(
            "cp.async.bulk.shared::cta.global.mbarrier::complete_tx::bytes "
            "[%0], [%1], %2, [%3];"
            :: "r"(sb), "l"(src + c0 + (long long)j * step), "r"(CHUNK), "r"(mb)
            : "memory");
    }

    // ── Steady state.
    for (int j = 0; j < n; ++j) {
        const int buf = j % NBUF;
        const uint32_t mb = mb_base + buf * 8;
        const uint32_t sb = sbase   + buf * CHUNK;
        const uint32_t parity = (uint32_t)((j / NBUF) & 1);

        // Wait for load j to land in smem.
        uint32_t done;
        asm volatile(
            "{\n\t.reg .pred p;\n\t"
            "mbarrier.try_wait.parity.acquire.cta.shared::cta.b64 p, [%1], %2;\n\t"
            "selp.b32 %0, 1, 0, p;\n\t}"
            : "=r"(done) : "r"(mb), "r"(parity) : "memory");
        if (!done) {
            asm volatile(
                "{\n\t.reg .pred P1;\n\t"
                "WAIT_LOOP_%=:\n\t"
                "mbarrier.try_wait.parity.acquire.cta.shared::cta.b64 P1, [%0], %1, 0x989680;\n\t"
                "@P1 bra.uni WAIT_DONE_%=;\n\t"
                "bra.uni WAIT_LOOP_%=;\n\t"
                "WAIT_DONE_%=:\n\t}"
                :: "r"(mb), "r"(parity) : "memory");
        }

        // Bulk store j (async, fire-and-forget into its own bulk group).
        asm volatile(
            "cp.async.bulk.global.shared::cta.bulk_group [%0], [%1], %2;"
            :: "l"(dst + c0 + (long long)j * step), "r"(sb), "r"(CHUNK)
            : "memory");
        asm volatile("cp.async.bulk.commit_group;" ::: "memory");

        // Refill: load j+LOOKAHEAD reuses buffer (j+LOOKAHEAD)%NBUF =
        // (j-1)%NBUF, whose store was committed last iteration.
        // wait_group.read 1 ensures every store except the newest (store j)
        // has finished READING smem; global writes continue asynchronously.
        const int jn = j + LOOKAHEAD;
        if (jn < n) {
            asm volatile("cp.async.bulk.wait_group.read 1;" ::: "memory");
            const int bufn = jn % NBUF;
            const uint32_t mb2 = mb_base + bufn * 8;
            const uint32_t sb2 = sbase   + bufn * CHUNK;
            asm volatile("mbarrier.arrive.expect_tx.shared.b64 _, [%0], %1;"
                         :: "r"(mb2), "r"(CHUNK) : "memory");
            asm volatile(
                "cp.async.bulk.shared::cta.global.mbarrier::complete_tx::bytes "
                "[%0], [%1], %2, [%3];"
                :: "r"(sb2), "l"(src + c0 + (long long)jn * step), "r"(CHUNK),
                   "r"(mb2)
                : "memory");
        }
    }

    // All bulk stores must fully complete (global writes done) before exit.
    asm volatile("cp.async.bulk.wait_group 0;" ::: "memory");
}

extern "C" void kernel_launch(void* const* d_in, const int* in_sizes, int n_in,
                              void* d_out, int out_size) {
    const float* x              = (const float*)d_in[0];
    const float* fingerprints   = (const float*)d_in[1];
    const float* cached_outputs = (const float*)d_in[2];
    float* out = (float*)d_out;

    static bool attr_set = false;
    if (!attr_set) {
        cudaFuncSetAttribute(tma_copy_kernel,
                             cudaFuncAttributeMaxDynamicSharedMemorySize,
                             SMEM_BYTES);
        attr_set = true;
    }
    tma_copy_kernel<<<GRID, 32, SMEM_BYTES>>>(x, fingerprints, cached_outputs,
                                              out);
}